// round 1
// baseline (speedup 1.0000x reference)
#include <cuda_runtime.h>
#include <cuda_bf16.h>

// Problem constants (from reference): T=64, B=512, H=512, SEQ=384 (unused).
#define T_DIM 64
#define B_DIM 512
#define H_DIM 512
#define H4    (H_DIM / 4)          // 128 float4 per row
#define MAX_LVL 66                 // pos <= T, write level <= T+1

// Scratch: source-time index per (t,b). -1 => initial_hidden.
__device__ int g_src[T_DIM * B_DIM];

// Kernel 1: replay ops per batch lane; only index bookkeeping, no float data.
__global__ void sim_kernel(const int* __restrict__ ops) {
    int b = blockIdx.x * blockDim.x + threadIdx.x;
    if (b >= B_DIM) return;

    short src[MAX_LVL];
    src[0] = -1;                   // level 0 = initial_hidden
    int pos = 0;
    #pragma unroll 1
    for (int t = 0; t < T_DIM; ++t) {
        int op = ops[t * B_DIM + b];
        src[pos + 1] = (short)t;   // scatter-write x_t at pos+1
        pos += op;                 // pos update (guaranteed >= 0 by input)
        g_src[t * B_DIM + b] = (int)src[pos];  // gather at new pos
    }
}

// Kernel 2: streaming gather-copy. One float4 per thread.
// idx layout: [t*B + b][h4], h4 in low 7 bits -> coalesced 512B per tb-tile.
__global__ void gather_kernel(const float4* __restrict__ inputs,
                              const float4* __restrict__ init_h,
                              float4* __restrict__ out) {
    unsigned idx = blockIdx.x * blockDim.x + threadIdx.x;
    // total = T*B*H4 = 4,194,304; grid sized exactly, no bounds check needed
    unsigned h4 = idx & (H4 - 1);
    unsigned tb = idx >> 7;            // t*B + b
    unsigned b  = tb & (B_DIM - 1);
    int s = __ldg(&g_src[tb]);         // uniform across the 128-thread tile
    float4 v;
    if (s < 0) {
        v = init_h[h4];
    } else {
        v = inputs[((unsigned)s * B_DIM + b) * H4 + h4];
    }
    out[idx] = v;
}

extern "C" void kernel_launch(void* const* d_in, const int* in_sizes, int n_in,
                              void* d_out, int out_size) {
    const float* inputs = (const float*)d_in[0];        // (T,B,H) f32
    const float* init_h = (const float*)d_in[1];        // (H,)   f32
    const int*   ops    = (const int*)d_in[2];          // (T,B)  i32
    float* out = (float*)d_out;                         // (T,B,H) f32

    sim_kernel<<<(B_DIM + 255) / 256, 256>>>(ops);

    const unsigned total4 = T_DIM * B_DIM * H4;         // 4,194,304
    const int threads = 256;
    gather_kernel<<<total4 / threads, threads>>>(
        (const float4*)inputs, (const float4*)init_h, (float4*)out);
}

// round 2
// speedup vs baseline: 2.8190x; 2.8190x over previous
#include <cuda_runtime.h>
#include <cuda_bf16.h>

// Problem constants: T=64, B=512, H=512 (SEQ unused beyond bounding the stack).
#define T_DIM 64
#define B_DIM 512
#define H_DIM 512
#define H4    (H_DIM / 4)          // 128 float4 per row

// One block per batch lane b. Phase 1: replay ops (index bookkeeping only,
// stack in shared, LDS only on pops). Phase 2: streaming gather-copy.
__global__ void __launch_bounds__(512) fused_kernel(
    const float4* __restrict__ inputs,   // (T,B,H) as float4
    const float4* __restrict__ init_h,   // (H,)   as float4
    const int*    __restrict__ ops,      // (T,B)
    float4*       __restrict__ out)      // (T,B,H) as float4
{
    __shared__ int s_ops[T_DIM];
    __shared__ int s_stack[T_DIM + 2];
    __shared__ int s_src[T_DIM];         // source time per t; -1 => init_h

    const int b   = blockIdx.x;
    const int tid = threadIdx.x;

    if (tid < T_DIM) s_ops[tid] = ops[tid * B_DIM + b];
    __syncthreads();

    if (tid == 0) {
        int pos = 0;
        int cur = -1;                    // value currently at stack[pos]
        s_stack[0] = -1;
        #pragma unroll
        for (int t = 0; t < T_DIM; ++t) {
            int op = s_ops[t];
            s_stack[pos + 1] = t;        // scatter-write x_t at pos+1
            pos += op;
            if (op == 1)       cur = t;              // just-written level
            else if (op == -1) cur = s_stack[pos];   // pop: read below (LDS)
            /* op == 0: cur unchanged (write went to pos+1, not pos) */
            s_src[t] = cur;
        }
    }
    __syncthreads();

    // Copy 64 rows x 128 float4 = 8192 float4 with 512 threads -> 16 each.
    // Per thread: h4 is FIXED, t = tid/128 + 4*i  (coalesced on both sides).
    const int h4 = tid & (H4 - 1);
    const int t0 = tid >> 7;                    // 0..3
    const float4 vinit = init_h[h4];            // tiny, L2/L1 resident

    #pragma unroll 4
    for (int i = 0; i < 16; ++i) {
        int t = t0 + (i << 2);                  // t0 + 4*i
        int s = s_src[t];
        float4 v;
        if (s < 0) {
            v = vinit;
        } else {
            v = inputs[((unsigned)(s * B_DIM + b)) * H4 + h4];
        }
        out[((unsigned)(t * B_DIM + b)) * H4 + h4] = v;
    }
}

extern "C" void kernel_launch(void* const* d_in, const int* in_sizes, int n_in,
                              void* d_out, int out_size) {
    const float* inputs = (const float*)d_in[0];   // (T,B,H) f32
    const float* init_h = (const float*)d_in[1];   // (H,)    f32
    const int*   ops    = (const int*)d_in[2];     // (T,B)   i32
    float* out = (float*)d_out;                    // (T,B,H) f32

    fused_kernel<<<B_DIM, 512>>>(
        (const float4*)inputs, (const float4*)init_h, ops, (float4*)out);
}